// round 3
// baseline (speedup 1.0000x reference)
#include <cuda_runtime.h>
#include <cstdint>

#define TOKENS     256
#define IN_F       4096
#define OUT_F      4096
#define NUM_CHUNKS 16384
#define CHUNK_SIZE 1024
#define D_ALPHA    64
#define HIDDEN     256

// Scratch (static device globals: allocation-free per harness rules)
__device__ float g_h[NUM_CHUNKS * HIDDEN];   // 16 MB: gelu(codebook@w1^T+b1)
__device__ float g_w[OUT_F * IN_F];          // 64 MB: generated weight, row-major (OUT_F, IN_F)

// ---------------------------------------------------------------------------
// helpers
// ---------------------------------------------------------------------------
__device__ __forceinline__ uint32_t f2tf32(float x) {
    uint32_t r;
    asm("cvt.rna.tf32.f32 %0, %1;" : "=r"(r) : "f"(x));
    return r;
}

__device__ __forceinline__ void mma_tf32(float d[4], const uint32_t a[4],
                                         const uint32_t b[2], const float c[4]) {
    asm volatile(
        "mma.sync.aligned.m16n8k8.row.col.f32.tf32.tf32.f32 "
        "{%0,%1,%2,%3}, {%4,%5,%6,%7}, {%8,%9}, {%10,%11,%12,%13};\n"
        : "=f"(d[0]), "=f"(d[1]), "=f"(d[2]), "=f"(d[3])
        : "r"(a[0]), "r"(a[1]), "r"(a[2]), "r"(a[3]),
          "r"(b[0]), "r"(b[1]),
          "f"(c[0]), "f"(c[1]), "f"(c[2]), "f"(c[3]));
}

__device__ __forceinline__ void cp_async16(void* dst, const void* src) {
    uint32_t s = (uint32_t)__cvta_generic_to_shared(dst);
    asm volatile("cp.async.cg.shared.global [%0], [%1], 16;\n" :: "r"(s), "l"(src));
}
__device__ __forceinline__ void cp_commit() {
    asm volatile("cp.async.commit_group;\n" ::: "memory");
}
__device__ __forceinline__ void cp_wait0() {
    asm volatile("cp.async.wait_group 0;\n" ::: "memory");
}

// ---------------------------------------------------------------------------
// Kernel 1: h = gelu(codebook @ w1^T + b1)   (16384 x 256, K = 64) in fp32
// One block = 8 codebook rows; each thread owns one hidden unit (its w1 row).
// ---------------------------------------------------------------------------
__global__ __launch_bounds__(256) void h_kernel(const float* __restrict__ cb,
                                                const float* __restrict__ w1,
                                                const float* __restrict__ b1) {
    const int tid = threadIdx.x;
    const int rowBase = blockIdx.x * 8;

    __shared__ float s_cb[8][D_ALPHA];
    #pragma unroll
    for (int i = tid; i < 8 * D_ALPHA; i += 256)
        s_cb[i >> 6][i & 63] = cb[(size_t)rowBase * D_ALPHA + i];

    float wr[D_ALPHA];
    const float4* w1v = (const float4*)(w1 + (size_t)tid * D_ALPHA);
    #pragma unroll
    for (int i = 0; i < D_ALPHA / 4; i++) {
        float4 v = w1v[i];
        wr[4 * i] = v.x; wr[4 * i + 1] = v.y; wr[4 * i + 2] = v.z; wr[4 * i + 3] = v.w;
    }
    const float bb = b1[tid];
    __syncthreads();

    #pragma unroll
    for (int r = 0; r < 8; r++) {
        float acc = bb;
        #pragma unroll
        for (int k = 0; k < D_ALPHA; k++)
            acc = fmaf(s_cb[r][k], wr[k], acc);
        // exact gelu
        float gel = 0.5f * acc * (1.0f + erff(acc * 0.70710678118654752f));
        g_h[(size_t)(rowBase + r) * HIDDEN + tid] = gel;
    }
}

// ---------------------------------------------------------------------------
// tf32 GEMM: C[M,N] = A[M,K] @ B[N,K]^T + bias[N]
// CTA tile 128x64, BK=16, 128 threads (4 warps of 64x32), double-buffered
// cp.async, smem rows padded to 20 floats (conflict-free fragment LDS).
// All dims divide tiles exactly for both call sites.
// ---------------------------------------------------------------------------
template <int K, int LDA, int LDB, int LDC>
__device__ __forceinline__ void gemm_body(const float* __restrict__ A,
                                          const float* __restrict__ B,
                                          const float* __restrict__ bias,
                                          float* __restrict__ C) {
    constexpr int BK = 16;
    constexpr int PAD = 20;
    constexpr int KT = K / BK;

    __shared__ __align__(16) float As[2][128 * PAD];
    __shared__ __align__(16) float Bs[2][64 * PAD];

    const int tid  = threadIdx.x;
    const int bm   = blockIdx.y * 128;
    const int bn   = blockIdx.x * 64;
    const int lane = tid & 31;
    const int wid  = tid >> 5;
    const int warpM = (wid & 1) * 64;
    const int warpN = (wid >> 1) * 32;
    const int g = lane >> 2;
    const int t = lane & 3;

    const int lrow = tid >> 2;        // 0..31
    const int lcol = (tid & 3) * 4;   // 0,4,8,12

    float acc[4][4][4];
    #pragma unroll
    for (int m = 0; m < 4; m++)
        #pragma unroll
        for (int n = 0; n < 4; n++)
            #pragma unroll
            for (int i = 0; i < 4; i++)
                acc[m][n][i] = 0.0f;

    auto load_tile = [&](int kt, int buf) {
        const float* Ag = A + (size_t)(bm + lrow) * LDA + kt * BK + lcol;
        float* Ad = &As[buf][lrow * PAD + lcol];
        #pragma unroll
        for (int i = 0; i < 4; i++)
            cp_async16(Ad + i * 32 * PAD, Ag + (size_t)i * 32 * LDA);
        const float* Bg = B + (size_t)(bn + lrow) * LDB + kt * BK + lcol;
        float* Bd = &Bs[buf][lrow * PAD + lcol];
        #pragma unroll
        for (int i = 0; i < 2; i++)
            cp_async16(Bd + i * 32 * PAD, Bg + (size_t)i * 32 * LDB);
        cp_commit();
    };

    load_tile(0, 0);

    for (int kt = 0; kt < KT; kt++) {
        cp_wait0();
        __syncthreads();
        if (kt + 1 < KT) load_tile(kt + 1, (kt + 1) & 1);

        const float* Asb = As[kt & 1];
        const float* Bsb = Bs[kt & 1];

        #pragma unroll
        for (int k0 = 0; k0 < BK; k0 += 8) {
            uint32_t af[4][4];
            uint32_t bf[4][2];
            #pragma unroll
            for (int m = 0; m < 4; m++) {
                const float* p = Asb + (warpM + m * 16 + g) * PAD + k0 + t;
                af[m][0] = f2tf32(p[0]);
                af[m][1] = f2tf32(p[8 * PAD]);
                af[m][2] = f2tf32(p[4]);
                af[m][3] = f2tf32(p[8 * PAD + 4]);
            }
            #pragma unroll
            for (int n = 0; n < 4; n++) {
                const float* p = Bsb + (warpN + n * 8 + g) * PAD + k0 + t;
                bf[n][0] = f2tf32(p[0]);
                bf[n][1] = f2tf32(p[4]);
            }
            #pragma unroll
            for (int m = 0; m < 4; m++)
                #pragma unroll
                for (int n = 0; n < 4; n++)
                    mma_tf32(acc[m][n], af[m], bf[n], acc[m][n]);
        }
        __syncthreads();
    }

    // epilogue: add bias, store fp32
    #pragma unroll
    for (int m = 0; m < 4; m++) {
        const int r0 = bm + warpM + m * 16 + g;
        #pragma unroll
        for (int n = 0; n < 4; n++) {
            const int c0 = bn + warpN + n * 8 + 2 * t;
            const float bv0 = bias[c0];
            const float bv1 = bias[c0 + 1];
            C[(size_t)r0 * LDC + c0]           = acc[m][n][0] + bv0;
            C[(size_t)r0 * LDC + c0 + 1]       = acc[m][n][1] + bv1;
            C[(size_t)(r0 + 8) * LDC + c0]     = acc[m][n][2] + bv0;
            C[(size_t)(r0 + 8) * LDC + c0 + 1] = acc[m][n][3] + bv1;
        }
    }
}

// Kernel 2: w (as chunks 16384x1024) = g_h @ w2^T + b2
__global__ __launch_bounds__(128) void gemm_chunks_kernel(const float* __restrict__ w2,
                                                          const float* __restrict__ b2) {
    gemm_body<HIDDEN, HIDDEN, HIDDEN, CHUNK_SIZE>(g_h, w2, b2, g_w);
}

// Kernel 3: out = x @ w^T + bias   (256 x 4096, K = 4096)
__global__ __launch_bounds__(128) void gemm_out_kernel(const float* __restrict__ x,
                                                       const float* __restrict__ bias,
                                                       float* __restrict__ out) {
    gemm_body<IN_F, IN_F, IN_F, OUT_F>(x, g_w, bias, out);
}

// ---------------------------------------------------------------------------
extern "C" void kernel_launch(void* const* d_in, const int* in_sizes, int n_in,
                              void* d_out, int out_size) {
    const float* x    = (const float*)d_in[0];  // (256, 4096)
    const float* cb   = (const float*)d_in[1];  // (16384, 64)
    const float* w1   = (const float*)d_in[2];  // (256, 64)
    const float* b1   = (const float*)d_in[3];  // (256,)
    const float* w2   = (const float*)d_in[4];  // (1024, 256)
    const float* b2   = (const float*)d_in[5];  // (1024,)
    const float* bias = (const float*)d_in[6];  // (4096,)
    float* out = (float*)d_out;                 // (256, 4096)

    h_kernel<<<NUM_CHUNKS / 8, 256>>>(cb, w1, b1);

    gemm_chunks_kernel<<<dim3(CHUNK_SIZE / 64, NUM_CHUNKS / 128), 128>>>(w2, b2);

    gemm_out_kernel<<<dim3(OUT_F / 64, TOKENS / 128), 128>>>(x, bias, out);
}

// round 7
// speedup vs baseline: 2.3838x; 2.3838x over previous
#include <cuda_runtime.h>
#include <cstdint>

#define TOKENS     256
#define IN_F       4096
#define OUT_F      4096
#define NUM_CHUNKS 16384
#define CHUNK_SIZE 1024
#define D_ALPHA    64
#define HIDDEN     256

// Scratch (static device globals: allocation-free per harness rules)
__device__ float g_h[NUM_CHUNKS * HIDDEN];      // 16 MB: gelu(cb@w1^T+b1); == H2 (4096,1024)
__device__ float g_w2t[HIDDEN * CHUNK_SIZE];    // 1 MB: w2 transposed (256, 1024)
__device__ float g_y[TOKENS * CHUNK_SIZE];      // 1 MB: y2 (256, 1024), col block c at c*256
__device__ float g_S[TOKENS];                   // per-token b2 contribution

// ---------------------------------------------------------------------------
// helpers
// ---------------------------------------------------------------------------
__device__ __forceinline__ uint32_t f2tf32(float x) {
    uint32_t r;
    asm("cvt.rna.tf32.f32 %0, %1;" : "=r"(r) : "f"(x));
    return r;
}

__device__ __forceinline__ void mma_tf32(float d[4], const uint32_t a[4],
                                         const uint32_t b[2], const float c[4]) {
    asm volatile(
        "mma.sync.aligned.m16n8k8.row.col.f32.tf32.tf32.f32 "
        "{%0,%1,%2,%3}, {%4,%5,%6,%7}, {%8,%9}, {%10,%11,%12,%13};\n"
        : "=f"(d[0]), "=f"(d[1]), "=f"(d[2]), "=f"(d[3])
        : "r"(a[0]), "r"(a[1]), "r"(a[2]), "r"(a[3]),
          "r"(b[0]), "r"(b[1]),
          "f"(c[0]), "f"(c[1]), "f"(c[2]), "f"(c[3]));
}

__device__ __forceinline__ void cp_async16(void* dst, const void* src) {
    uint32_t s = (uint32_t)__cvta_generic_to_shared(dst);
    asm volatile("cp.async.cg.shared.global [%0], [%1], 16;\n" :: "r"(s), "l"(src));
}
__device__ __forceinline__ void cp_commit() {
    asm volatile("cp.async.commit_group;\n" ::: "memory");
}
__device__ __forceinline__ void cp_wait0() {
    asm volatile("cp.async.wait_group 0;\n" ::: "memory");
}

// Epilogue modes
#define EPI_NONE     0   // C = acc
#define EPI_BIAS     1   // C = acc + bias[n]
#define EPI_GELU     2   // C = gelu(acc + bias[n])
#define EPI_BIAS_ROW 3   // C = acc + bias[n] + rowadd[m]

__device__ __forceinline__ float gelu_exact(float v) {
    return 0.5f * v * (1.0f + erff(v * 0.70710678118654752f));
}

// ---------------------------------------------------------------------------
// tf32 GEMM: C[M,N] = A[M,K] @ B[N,K]^T (+epilogue)
// CTA tile 128x64, BK=16, 128 threads (4 warps of 64x32), double-buffered
// cp.async, smem rows padded to 20 floats (conflict-free fragment LDS).
// All dims divide tiles exactly for all call sites.
// ---------------------------------------------------------------------------
template <int K, int LDA, int LDB, int LDC, int EPI>
__device__ __forceinline__ void gemm_body(const float* __restrict__ A,
                                          const float* __restrict__ B,
                                          const float* __restrict__ bias,
                                          const float* __restrict__ rowadd,
                                          float* __restrict__ C) {
    constexpr int BK = 16;
    constexpr int PAD = 20;
    constexpr int KT = K / BK;

    __shared__ __align__(16) float As[2][128 * PAD];
    __shared__ __align__(16) float Bs[2][64 * PAD];

    const int tid  = threadIdx.x;
    const int bm   = blockIdx.y * 128;
    const int bn   = blockIdx.x * 64;
    const int lane = tid & 31;
    const int wid  = tid >> 5;
    const int warpM = (wid & 1) * 64;
    const int warpN = (wid >> 1) * 32;
    const int g = lane >> 2;
    const int t = lane & 3;

    const int lrow = tid >> 2;        // 0..31
    const int lcol = (tid & 3) * 4;   // 0,4,8,12

    float acc[4][4][4];
    #pragma unroll
    for (int m = 0; m < 4; m++)
        #pragma unroll
        for (int n = 0; n < 4; n++)
            #pragma unroll
            for (int i = 0; i < 4; i++)
                acc[m][n][i] = 0.0f;

    auto load_tile = [&](int kt, int buf) {
        const float* Ag = A + (size_t)(bm + lrow) * LDA + kt * BK + lcol;
        float* Ad = &As[buf][lrow * PAD + lcol];
        #pragma unroll
        for (int i = 0; i < 4; i++)
            cp_async16(Ad + i * 32 * PAD, Ag + (size_t)i * 32 * LDA);
        const float* Bg = B + (size_t)(bn + lrow) * LDB + kt * BK + lcol;
        float* Bd = &Bs[buf][lrow * PAD + lcol];
        #pragma unroll
        for (int i = 0; i < 2; i++)
            cp_async16(Bd + i * 32 * PAD, Bg + (size_t)i * 32 * LDB);
        cp_commit();
    };

    load_tile(0, 0);

    for (int kt = 0; kt < KT; kt++) {
        cp_wait0();
        __syncthreads();
        if (kt + 1 < KT) load_tile(kt + 1, (kt + 1) & 1);

        const float* Asb = As[kt & 1];
        const float* Bsb = Bs[kt & 1];

        #pragma unroll
        for (int k0 = 0; k0 < BK; k0 += 8) {
            uint32_t af[4][4];
            uint32_t bf[4][2];
            #pragma unroll
            for (int m = 0; m < 4; m++) {
                const float* p = Asb + (warpM + m * 16 + g) * PAD + k0 + t;
                af[m][0] = f2tf32(p[0]);
                af[m][1] = f2tf32(p[8 * PAD]);
                af[m][2] = f2tf32(p[4]);
                af[m][3] = f2tf32(p[8 * PAD + 4]);
            }
            #pragma unroll
            for (int n = 0; n < 4; n++) {
                const float* p = Bsb + (warpN + n * 8 + g) * PAD + k0 + t;
                bf[n][0] = f2tf32(p[0]);
                bf[n][1] = f2tf32(p[4]);
            }
            #pragma unroll
            for (int m = 0; m < 4; m++)
                #pragma unroll
                for (int n = 0; n < 4; n++)
                    mma_tf32(acc[m][n], af[m], bf[n], acc[m][n]);
        }
        __syncthreads();
    }

    // epilogue
    #pragma unroll
    for (int m = 0; m < 4; m++) {
        const int r0 = bm + warpM + m * 16 + g;
        float ra0 = 0.0f, ra1 = 0.0f;
        if (EPI == EPI_BIAS_ROW) { ra0 = rowadd[r0]; ra1 = rowadd[r0 + 8]; }
        #pragma unroll
        for (int n = 0; n < 4; n++) {
            const int c0 = bn + warpN + n * 8 + 2 * t;
            float bv0 = 0.0f, bv1 = 0.0f;
            if (EPI != EPI_NONE) { bv0 = bias[c0]; bv1 = bias[c0 + 1]; }
            float v00 = acc[m][n][0] + bv0 + ra0;
            float v01 = acc[m][n][1] + bv1 + ra0;
            float v10 = acc[m][n][2] + bv0 + ra1;
            float v11 = acc[m][n][3] + bv1 + ra1;
            if (EPI == EPI_GELU) {
                v00 = gelu_exact(v00); v01 = gelu_exact(v01);
                v10 = gelu_exact(v10); v11 = gelu_exact(v11);
            }
            C[(size_t)r0 * LDC + c0]           = v00;
            C[(size_t)r0 * LDC + c0 + 1]       = v01;
            C[(size_t)(r0 + 8) * LDC + c0]     = v10;
            C[(size_t)(r0 + 8) * LDC + c0 + 1] = v11;
        }
    }
}

// ---------------------------------------------------------------------------
// Kernel 1: h = gelu(codebook @ w1^T + b1)   M=16384, N=256, K=64
// ---------------------------------------------------------------------------
__global__ __launch_bounds__(128) void h_gemm_kernel(const float* __restrict__ cb,
                                                     const float* __restrict__ w1,
                                                     const float* __restrict__ b1) {
    gemm_body<D_ALPHA, D_ALPHA, D_ALPHA, HIDDEN, EPI_GELU>(cb, w1, b1, nullptr, g_h);
}

// ---------------------------------------------------------------------------
// Kernel 2: transpose w2 (1024,256) -> g_w2t (256,1024)
// ---------------------------------------------------------------------------
__global__ __launch_bounds__(256) void transpose_w2_kernel(const float* __restrict__ w2) {
    __shared__ float tile[32][33];
    const int m0 = blockIdx.x * 32;   // column block in w2 (0..255)
    const int j0 = blockIdx.y * 32;   // row block in w2 (0..1023)
    const int tx = threadIdx.x;       // 0..31
    const int ty = threadIdx.y;       // 0..7
    #pragma unroll
    for (int i = 0; i < 32; i += 8)
        tile[ty + i][tx] = w2[(size_t)(j0 + ty + i) * HIDDEN + m0 + tx];
    __syncthreads();
    #pragma unroll
    for (int i = 0; i < 32; i += 8)
        g_w2t[(size_t)(m0 + ty + i) * CHUNK_SIZE + j0 + tx] = tile[tx][ty + i];
}

// ---------------------------------------------------------------------------
// Kernel 3: S[t] = sum_j b2[j] * (x[t,j] + x[t,j+1024] + x[t,j+2048] + x[t,j+3072])
// ---------------------------------------------------------------------------
__global__ __launch_bounds__(256) void s_kernel(const float* __restrict__ x,
                                                const float* __restrict__ b2) {
    const int t = blockIdx.x;
    const int tid = threadIdx.x;
    const float* xr = x + (size_t)t * IN_F;
    float a = 0.0f;
    #pragma unroll
    for (int j = tid; j < CHUNK_SIZE; j += 256) {
        float xs = xr[j] + xr[j + 1024] + xr[j + 2048] + xr[j + 3072];
        a = fmaf(b2[j], xs, a);
    }
    // reduce
    #pragma unroll
    for (int off = 16; off > 0; off >>= 1)
        a += __shfl_xor_sync(0xffffffffu, a, off);
    __shared__ float sred[8];
    if ((tid & 31) == 0) sred[tid >> 5] = a;
    __syncthreads();
    if (tid == 0) {
        float s = 0.0f;
        #pragma unroll
        for (int i = 0; i < 8; i++) s += sred[i];
        g_S[t] = s;
    }
}

// ---------------------------------------------------------------------------
// Kernel 4: y_c = x[:, c*1024:(c+1)*1024] @ w2t^T   -> g_y[:, c*256:(c+1)*256]
//           M=256, N=256, K=1024, batched over c via blockIdx.z
// ---------------------------------------------------------------------------
__global__ __launch_bounds__(128) void y_gemm_kernel(const float* __restrict__ x) {
    const int c = blockIdx.z;
    gemm_body<CHUNK_SIZE, IN_F, CHUNK_SIZE, CHUNK_SIZE, EPI_NONE>(
        x + c * CHUNK_SIZE, g_w2t, nullptr, nullptr, g_y + c * HIDDEN);
}

// ---------------------------------------------------------------------------
// Kernel 5: out = g_y @ g_h(reshaped 4096x1024)^T + bias[o] + S[t]
//           M=256, N=4096, K=1024
// ---------------------------------------------------------------------------
__global__ __launch_bounds__(128) void out_gemm_kernel(const float* __restrict__ bias,
                                                       float* __restrict__ out) {
    gemm_body<CHUNK_SIZE, CHUNK_SIZE, CHUNK_SIZE, OUT_F, EPI_BIAS_ROW>(
        g_y, g_h, bias, g_S, out);
}

// ---------------------------------------------------------------------------
extern "C" void kernel_launch(void* const* d_in, const int* in_sizes, int n_in,
                              void* d_out, int out_size) {
    const float* x    = (const float*)d_in[0];  // (256, 4096)
    const float* cb   = (const float*)d_in[1];  // (16384, 64)
    const float* w1   = (const float*)d_in[2];  // (256, 64)
    const float* b1   = (const float*)d_in[3];  // (256,)
    const float* w2   = (const float*)d_in[4];  // (1024, 256)
    const float* b2   = (const float*)d_in[5];  // (1024,)
    const float* bias = (const float*)d_in[6];  // (4096,)
    float* out = (float*)d_out;                 // (256, 4096)

    // h = gelu(cb @ w1^T + b1): grid (N/64=4, M/128=128)
    h_gemm_kernel<<<dim3(HIDDEN / 64, NUM_CHUNKS / 128), 128>>>(cb, w1, b1);

    // w2^T and S[t] (independent)
    transpose_w2_kernel<<<dim3(HIDDEN / 32, CHUNK_SIZE / 32), dim3(32, 8)>>>(w2);
    s_kernel<<<TOKENS, 256>>>(x, b2);

    // y: grid (N/64=4, M/128=2, c=4)
    y_gemm_kernel<<<dim3(HIDDEN / 64, TOKENS / 128, 4), 128>>>(x);

    // out: grid (N/64=64, M/128=2)
    out_gemm_kernel<<<dim3(OUT_F / 64, TOKENS / 128), 128>>>(bias, out);
}

// round 9
// speedup vs baseline: 5.1340x; 2.1537x over previous
#include <cuda_runtime.h>
#include <cstdint>

#define TOKENS     256
#define IN_F       4096
#define OUT_F      4096
#define NUM_CHUNKS 16384
#define CHUNK_SIZE 1024
#define D_ALPHA    64
#define HIDDEN     256

#define Y_SPLITS   8    // K=1024 -> 8 x 128
#define O_SPLITS   4    // K=1024 -> 4 x 256

// Scratch (static device globals: allocation-free per harness rules)
__device__ float g_h[NUM_CHUNKS * HIDDEN];              // 16 MB; == H2 (4096,1024)
__device__ float g_w2t[HIDDEN * CHUNK_SIZE];            // 1 MB: w2^T (256, 1024)
__device__ float g_y[TOKENS * CHUNK_SIZE];              // 1 MB: y (256, 1024)
__device__ float g_S[TOKENS];                           // per-token b2 contribution
__device__ float g_ypart[Y_SPLITS][TOKENS * CHUNK_SIZE]; // 8 MB split-K partials for y
__device__ float g_opart[O_SPLITS][TOKENS * OUT_F];      // 16 MB split-K partials for out

// ---------------------------------------------------------------------------
// helpers
// ---------------------------------------------------------------------------
__device__ __forceinline__ void mma_tf32(float d[4], const uint32_t a[4],
                                         const uint32_t b[2], const float c[4]) {
    asm volatile(
        "mma.sync.aligned.m16n8k8.row.col.f32.tf32.tf32.f32 "
        "{%0,%1,%2,%3}, {%4,%5,%6,%7}, {%8,%9}, {%10,%11,%12,%13};\n"
        : "=f"(d[0]), "=f"(d[1]), "=f"(d[2]), "=f"(d[3])
        : "r"(a[0]), "r"(a[1]), "r"(a[2]), "r"(a[3]),
          "r"(b[0]), "r"(b[1]),
          "f"(c[0]), "f"(c[1]), "f"(c[2]), "f"(c[3]));
}

__device__ __forceinline__ void cp_async16(void* dst, const void* src) {
    uint32_t s = (uint32_t)__cvta_generic_to_shared(dst);
    asm volatile("cp.async.cg.shared.global [%0], [%1], 16;\n" :: "r"(s), "l"(src));
}
__device__ __forceinline__ void cp_commit() {
    asm volatile("cp.async.commit_group;\n" ::: "memory");
}
__device__ __forceinline__ void cp_wait0() {
    asm volatile("cp.async.wait_group 0;\n" ::: "memory");
}

#define EPI_NONE 0
#define EPI_GELU 2

__device__ __forceinline__ float gelu_exact(float v) {
    return 0.5f * v * (1.0f + erff(v * 0.70710678118654752f));
}

// ---------------------------------------------------------------------------
// tf32 GEMM tile: C[128,64] (+epilogue) = A[128,K] @ B[64,K]^T
// BK=16, 128 threads (4 warps of 64x32), double-buffered cp.async,
// smem rows padded to 20 floats. fp32 bits fed raw to tf32 mma (HW truncates).
// ---------------------------------------------------------------------------
template <int KT, int LDA, int LDB, int LDC, int EPI>
__device__ __forceinline__ void gemm_body(const float* __restrict__ A,
                                          const float* __restrict__ B,
                                          const float* __restrict__ bias,
                                          float* __restrict__ C) {
    constexpr int BK = 16;
    constexpr int PAD = 20;

    __shared__ __align__(16) float As[2][128 * PAD];
    __shared__ __align__(16) float Bs[2][64 * PAD];

    const int tid  = threadIdx.x;
    const int bm   = blockIdx.y * 128;
    const int bn   = blockIdx.x * 64;
    const int lane = tid & 31;
    const int wid  = tid >> 5;
    const int warpM = (wid & 1) * 64;
    const int warpN = (wid >> 1) * 32;
    const int g = lane >> 2;
    const int t = lane & 3;

    const int lrow = tid >> 2;        // 0..31
    const int lcol = (tid & 3) * 4;   // 0,4,8,12

    float acc[4][4][4];
    #pragma unroll
    for (int m = 0; m < 4; m++)
        #pragma unroll
        for (int n = 0; n < 4; n++)
            #pragma unroll
            for (int i = 0; i < 4; i++)
                acc[m][n][i] = 0.0f;

    auto load_tile = [&](int kt, int buf) {
        const float* Ag = A + (size_t)(bm + lrow) * LDA + kt * BK + lcol;
        float* Ad = &As[buf][lrow * PAD + lcol];
        #pragma unroll
        for (int i = 0; i < 4; i++)
            cp_async16(Ad + i * 32 * PAD, Ag + (size_t)i * 32 * LDA);
        const float* Bg = B + (size_t)(bn + lrow) * LDB + kt * BK + lcol;
        float* Bd = &Bs[buf][lrow * PAD + lcol];
        #pragma unroll
        for (int i = 0; i < 2; i++)
            cp_async16(Bd + i * 32 * PAD, Bg + (size_t)i * 32 * LDB);
        cp_commit();
    };

    load_tile(0, 0);

    for (int kt = 0; kt < KT; kt++) {
        cp_wait0();
        __syncthreads();
        if (kt + 1 < KT) load_tile(kt + 1, (kt + 1) & 1);

        const float* Asb = As[kt & 1];
        const float* Bsb = Bs[kt & 1];

        #pragma unroll
        for (int k0 = 0; k0 < BK; k0 += 8) {
            uint32_t af[4][4];
            uint32_t bf[4][2];
            #pragma unroll
            for (int m = 0; m < 4; m++) {
                const float* p = Asb + (warpM + m * 16 + g) * PAD + k0 + t;
                af[m][0] = __float_as_uint(p[0]);
                af[m][1] = __float_as_uint(p[8 * PAD]);
                af[m][2] = __float_as_uint(p[4]);
                af[m][3] = __float_as_uint(p[8 * PAD + 4]);
            }
            #pragma unroll
            for (int n = 0; n < 4; n++) {
                const float* p = Bsb + (warpN + n * 8 + g) * PAD + k0 + t;
                bf[n][0] = __float_as_uint(p[0]);
                bf[n][1] = __float_as_uint(p[4]);
            }
            #pragma unroll
            for (int m = 0; m < 4; m++)
                #pragma unroll
                for (int n = 0; n < 4; n++)
                    mma_tf32(acc[m][n], af[m], bf[n], acc[m][n]);
        }
        __syncthreads();
    }

    // epilogue
    #pragma unroll
    for (int m = 0; m < 4; m++) {
        const int r0 = bm + warpM + m * 16 + g;
        #pragma unroll
        for (int n = 0; n < 4; n++) {
            const int c0 = bn + warpN + n * 8 + 2 * t;
            float bv0 = 0.0f, bv1 = 0.0f;
            if (EPI == EPI_GELU) { bv0 = bias[c0]; bv1 = bias[c0 + 1]; }
            float v00 = acc[m][n][0] + bv0;
            float v01 = acc[m][n][1] + bv1;
            float v10 = acc[m][n][2] + bv0;
            float v11 = acc[m][n][3] + bv1;
            if (EPI == EPI_GELU) {
                v00 = gelu_exact(v00); v01 = gelu_exact(v01);
                v10 = gelu_exact(v10); v11 = gelu_exact(v11);
            }
            C[(size_t)r0 * LDC + c0]           = v00;
            C[(size_t)r0 * LDC + c0 + 1]       = v01;
            C[(size_t)(r0 + 8) * LDC + c0]     = v10;
            C[(size_t)(r0 + 8) * LDC + c0 + 1] = v11;
        }
    }
}

// ---------------------------------------------------------------------------
// Kernel 1: h = gelu(codebook @ w1^T + b1)   M=16384, N=256, K=64
// ---------------------------------------------------------------------------
__global__ __launch_bounds__(128) void h_gemm_kernel(const float* __restrict__ cb,
                                                     const float* __restrict__ w1,
                                                     const float* __restrict__ b1) {
    gemm_body<D_ALPHA / 16, D_ALPHA, D_ALPHA, HIDDEN, EPI_GELU>(cb, w1, b1, g_h);
}

// ---------------------------------------------------------------------------
// Kernel 2: transpose w2 (1024,256) -> g_w2t (256,1024)
// ---------------------------------------------------------------------------
__global__ __launch_bounds__(256) void transpose_w2_kernel(const float* __restrict__ w2) {
    __shared__ float tile[32][33];
    const int m0 = blockIdx.x * 32;
    const int j0 = blockIdx.y * 32;
    const int tx = threadIdx.x;
    const int ty = threadIdx.y;
    #pragma unroll
    for (int i = 0; i < 32; i += 8)
        tile[ty + i][tx] = w2[(size_t)(j0 + ty + i) * HIDDEN + m0 + tx];
    __syncthreads();
    #pragma unroll
    for (int i = 0; i < 32; i += 8)
        g_w2t[(size_t)(m0 + ty + i) * CHUNK_SIZE + j0 + tx] = tile[tx][ty + i];
}

// ---------------------------------------------------------------------------
// Kernel 3: S[t] = sum_j b2[j] * sum_c x[t, c*1024 + j]
// ---------------------------------------------------------------------------
__global__ __launch_bounds__(256) void s_kernel(const float* __restrict__ x,
                                                const float* __restrict__ b2) {
    const int t = blockIdx.x;
    const int tid = threadIdx.x;
    const float* xr = x + (size_t)t * IN_F;
    float a = 0.0f;
    #pragma unroll
    for (int j = tid; j < CHUNK_SIZE; j += 256) {
        float xs = xr[j] + xr[j + 1024] + xr[j + 2048] + xr[j + 3072];
        a = fmaf(b2[j], xs, a);
    }
    #pragma unroll
    for (int off = 16; off > 0; off >>= 1)
        a += __shfl_xor_sync(0xffffffffu, a, off);
    __shared__ float sred[8];
    if ((tid & 31) == 0) sred[tid >> 5] = a;
    __syncthreads();
    if (tid == 0) {
        float s = 0.0f;
        #pragma unroll
        for (int i = 0; i < 8; i++) s += sred[i];
        g_S[t] = s;
    }
}

// ---------------------------------------------------------------------------
// Kernel 4: split-K y partials.
// z = c*Y_SPLITS + s: y_c partial over K slice [s*128, (s+1)*128)
// ---------------------------------------------------------------------------
__global__ __launch_bounds__(128) void y_gemm_split_kernel(const float* __restrict__ x) {
    const int z = blockIdx.z;
    const int c = z >> 3;           // 0..3
    const int s = z & (Y_SPLITS - 1);
    const float* A = x + c * CHUNK_SIZE + s * (CHUNK_SIZE / Y_SPLITS);
    const float* B = g_w2t + s * (CHUNK_SIZE / Y_SPLITS);
    float* C = g_ypart[s] + c * HIDDEN;
    gemm_body<(CHUNK_SIZE / Y_SPLITS) / 16, IN_F, CHUNK_SIZE, CHUNK_SIZE, EPI_NONE>(
        A, B, nullptr, C);
}

// Kernel 5: g_y = sum_s g_ypart[s]
__global__ __launch_bounds__(256) void reduce_y_kernel() {
    const int idx = blockIdx.x * 256 + threadIdx.x;   // float4 index
    float4 a = ((const float4*)g_ypart[0])[idx];
    #pragma unroll
    for (int s = 1; s < Y_SPLITS; s++) {
        float4 b = ((const float4*)g_ypart[s])[idx];
        a.x += b.x; a.y += b.y; a.z += b.z; a.w += b.w;
    }
    ((float4*)g_y)[idx] = a;
}

// ---------------------------------------------------------------------------
// Kernel 6: split-K out partials: out = g_y @ H2^T, H2 = g_h as (4096,1024)
// ---------------------------------------------------------------------------
__global__ __launch_bounds__(128) void out_gemm_split_kernel() {
    const int s = blockIdx.z;
    const float* A = g_y + s * (CHUNK_SIZE / O_SPLITS);
    const float* B = g_h + s * (CHUNK_SIZE / O_SPLITS);
    float* C = g_opart[s];
    gemm_body<(CHUNK_SIZE / O_SPLITS) / 16, CHUNK_SIZE, CHUNK_SIZE, OUT_F, EPI_NONE>(
        A, B, nullptr, C);
}

// Kernel 7: out = sum_s g_opart[s] + bias[o] + S[t]
__global__ __launch_bounds__(256) void reduce_out_kernel(const float* __restrict__ bias,
                                                         float* __restrict__ out) {
    const int idx = blockIdx.x * 256 + threadIdx.x;   // float4 index over (256,4096)
    const int t  = idx >> 10;                         // 4096/4 = 1024 f4 per row
    const int o4 = idx & 1023;
    float4 a = ((const float4*)g_opart[0])[idx];
    #pragma unroll
    for (int s = 1; s < O_SPLITS; s++) {
        float4 b = ((const float4*)g_opart[s])[idx];
        a.x += b.x; a.y += b.y; a.z += b.z; a.w += b.w;
    }
    const float4 bv = ((const float4*)bias)[o4];
    const float sv = g_S[t];
    a.x += bv.x + sv; a.y += bv.y + sv; a.z += bv.z + sv; a.w += bv.w + sv;
    ((float4*)out)[idx] = a;
}

// ---------------------------------------------------------------------------
extern "C" void kernel_launch(void* const* d_in, const int* in_sizes, int n_in,
                              void* d_out, int out_size) {
    const float* x    = (const float*)d_in[0];  // (256, 4096)
    const float* cb   = (const float*)d_in[1];  // (16384, 64)
    const float* w1   = (const float*)d_in[2];  // (256, 64)
    const float* b1   = (const float*)d_in[3];  // (256,)
    const float* w2   = (const float*)d_in[4];  // (1024, 256)
    const float* b2   = (const float*)d_in[5];  // (1024,)
    const float* bias = (const float*)d_in[6];  // (4096,)
    float* out = (float*)d_out;                 // (256, 4096)

    transpose_w2_kernel<<<dim3(HIDDEN / 32, CHUNK_SIZE / 32), dim3(32, 8)>>>(w2);
    s_kernel<<<TOKENS, 256>>>(x, b2);
    h_gemm_kernel<<<dim3(HIDDEN / 64, NUM_CHUNKS / 128), 128>>>(cb, w1, b1);

    // y split-K: grid (4 n-tiles, 2 m-tiles, 4c * 8 splits) = 256 CTAs
    y_gemm_split_kernel<<<dim3(HIDDEN / 64, TOKENS / 128, 4 * Y_SPLITS), 128>>>(x);
    reduce_y_kernel<<<(TOKENS * CHUNK_SIZE / 4) / 256, 256>>>();

    // out split-K: grid (64, 2, 4) = 512 CTAs
    out_gemm_split_kernel<<<dim3(OUT_F / 64, TOKENS / 128, O_SPLITS), 128>>>();
    reduce_out_kernel<<<(TOKENS * OUT_F / 4) / 256, 256>>>(bias, out);
}